// round 13
// baseline (speedup 1.0000x reference)
#include <cuda_runtime.h>
#include <cuda_fp16.h>
#include <math.h>
#include <stdint.h>

#define NROWS 16384      // 2 * 8*32*32
#define NCODE 4096
#define KDIM  256
#define SPB   8192       // spatial per batch
#define ZTOT  4194304    // 2*256*8192

// output layout: concatenation of reference outputs, float32
#define OFF_LOSS   0ull
#define OFF_ZQ     1ull
#define OFF_PERP   4194305ull
#define OFF_OH     4194306ull
#define OFF_IDX    71303170ull
#define OFF_ZOUT   71319554ull
#define OFF_EMA    75513858ull

// B operand pre-scale: 2^12 (exact). Descale folded into epilogue FMA as 2^-11.
#define BSCALE 4096.0f
// screening margin: |d_scalar - d_hh| <= ~1.5e-4 worst case; 5e-4 is 3x headroom
#define MARGIN 5e-4f
#define CAP 32

// ---------------- scratch ----------------
__device__ float  g_Anorm[NROWS];
__device__ float  g_Snorm[NCODE];
__device__ float  g_pd[NROWS * 32];
__device__ int    g_idx[NROWS];
__device__ int    g_cnt[NCODE];
__device__ double g_losspart[4096];

// fp16 hi operands packed in mma.m16n8k16 fragment order (half2 per reg).
// A: [mtile 0..1023][kc16 0..15][lane 0..31][4 regs]
// B: [ntile 0..511 ][kc16 0..15][lane 0..31][2 regs]   (scaled by BSCALE)
__device__ __align__(16) uint32_t g_Afh[(size_t)1024 * 16 * 32 * 4];
__device__ __align__(16) uint32_t g_Bfh[(size_t)512 * 16 * 32 * 2];

// ---------------- helpers ----------------
__device__ __forceinline__ uint32_t smem_u32(const void* p) {
    uint32_t a;
    asm("{ .reg .u64 t; cvta.to.shared.u64 t, %1; cvt.u32.u64 %0, t; }" : "=r"(a) : "l"(p));
    return a;
}
#define CP_ASYNC16(dst, src) \
    asm volatile("cp.async.cg.shared.global [%0], [%1], 16;" :: "r"(dst), "l"(src) : "memory")
#define CP_COMMIT() asm volatile("cp.async.commit_group;" ::: "memory")
#define CP_WAIT0()  asm volatile("cp.async.wait_group 0;" ::: "memory")

__device__ __forceinline__ void mma_f16(float* c, const uint32_t* a, const uint32_t* b) {
    asm volatile("mma.sync.aligned.m16n8k16.row.col.f32.f16.f16.f32 "
        "{%0,%1,%2,%3}, {%4,%5,%6,%7}, {%8,%9}, {%0,%1,%2,%3};"
        : "+f"(c[0]), "+f"(c[1]), "+f"(c[2]), "+f"(c[3])
        : "r"(a[0]), "r"(a[1]), "r"(a[2]), "r"(a[3]), "r"(b[0]), "r"(b[1]));
}

__device__ __forceinline__ uint32_t pack_hi2(float x, float y) {
    __half2 h = __halves2half2(__float2half_rn(x), __float2half_rn(y));
    return *(uint32_t*)&h;
}

// ---------------------------------------------------------------- init
__global__ void k_init() {
    int t = blockIdx.x * 256 + threadIdx.x;
    if (t < NCODE) g_cnt[t] = 0;
}

// ---------------------------------------------------------------- row norms ||z_n||^2
__global__ void k_rownorm(const float* __restrict__ z) {
    int n = blockIdx.x * 256 + threadIdx.x;
    int b = n >> 13, s = n & (SPB - 1);
    const float* p = z + (size_t)b * (KDIM * SPB) + s;
    float a = 0.f;
    #pragma unroll 8
    for (int c = 0; c < KDIM; c++) {
        float v = p[(size_t)c * SPB];
        a = __fmaf_rn(v, v, a);
    }
    g_Anorm[n] = a;
}

// ---------------------------------------------------------------- code norms ||e_j||^2
__global__ void k_codenorm(const float* __restrict__ E) {
    int w = blockIdx.x * 8 + (threadIdx.x >> 5);
    int lane = threadIdx.x & 31;
    const float* p = E + (size_t)w * KDIM;
    float a = 0.f;
    #pragma unroll
    for (int i = 0; i < 8; i++) {
        float v = p[lane + i * 32];
        a = __fmaf_rn(v, v, a);
    }
    #pragma unroll
    for (int off = 16; off > 0; off >>= 1)
        a += __shfl_xor_sync(0xffffffffu, a, off);
    if (lane == 0) g_Snorm[w] = a;
}

// ---------------------------------------------------------------- A fragment pack (hi only)
__global__ void k_packA(const float* __restrict__ z) {
    int tid = blockIdx.x * 256 + threadIdx.x;   // 524,288
    int l  = tid & 31;
    int kc = (tid >> 5) & 15;
    int T  = tid >> 9;                           // 0..1023
    int g = l >> 2, tg = l & 3;
    int m = T * 16;
    int b = m >> 13;
    int s = (m & (SPB - 1)) + g;
    int k0 = kc * 16 + tg * 2;
    const float* zb = z + ((size_t)b * KDIM * SPB);
    uint4 hi;
    hi.x = pack_hi2(zb[(size_t)k0 * SPB + s],       zb[(size_t)(k0 + 1) * SPB + s]);
    hi.y = pack_hi2(zb[(size_t)k0 * SPB + s + 8],   zb[(size_t)(k0 + 1) * SPB + s + 8]);
    hi.z = pack_hi2(zb[(size_t)(k0 + 8) * SPB + s], zb[(size_t)(k0 + 9) * SPB + s]);
    hi.w = pack_hi2(zb[(size_t)(k0 + 8) * SPB + s + 8], zb[(size_t)(k0 + 9) * SPB + s + 8]);
    size_t o = ((size_t)T * 16 + kc) * 128 + l * 4;
    *(uint4*)&g_Afh[o] = hi;
}

// ---------------------------------------------------------------- B fragment pack (scaled, hi only)
__global__ void k_packB(const float* __restrict__ E) {
    int tid = blockIdx.x * 256 + threadIdx.x;   // 262,144
    int l  = tid & 31;
    int kc = (tid >> 5) & 15;
    int nt = tid >> 9;                           // 0..511
    int g = l >> 2, tg = l & 3;
    int n = nt * 8 + g;
    int k0 = kc * 16 + tg * 2;
    size_t o = ((size_t)nt * 16 + kc) * 64 + l * 2;
    g_Bfh[o]     = pack_hi2(E[(size_t)n * KDIM + k0] * BSCALE,
                            E[(size_t)n * KDIM + k0 + 1] * BSCALE);
    g_Bfh[o + 1] = pack_hi2(E[(size_t)n * KDIM + k0 + 8] * BSCALE,
                            E[(size_t)n * KDIM + k0 + 9] * BSCALE);
}

// ---------------------------------------------------------------- mma GEMM (hh pass) + d store + row-min
// block tile 128x128, stage = k32 (2 k16-chunks), double buffered.
// stage layout: Ah[2kc][8mt][32lane][16B] 8K | Bh[2kc][16nt][32lane][8B] 8K
#define STG 16384
#define GSMEM (512 + 2 * STG)

__device__ __forceinline__ void copy_stage(char* sm_, int st, int ks, int bm, int bn, int t) {
    uint32_t sb = smem_u32(sm_ + 512 + st * STG);
    #pragma unroll
    for (int i = 0; i < 2; i++) {          // A: 512 chunks of 16B
        int c = t + i * 256;
        int kc = c >> 8, mt = (c >> 5) & 7, lane = c & 31;
        const uint32_t* src = g_Afh
            + (((size_t)(bm * 8 + mt) * 16 + ks * 2 + kc) * 32 + lane) * 4;
        CP_ASYNC16(sb + c * 16, src);
    }
    #pragma unroll
    for (int i = 0; i < 2; i++) {          // B: 512 chunks of 16B (2 lanes each)
        int c = t + i * 256;
        int u = c * 2;
        int kc = u >> 9, nt = (u >> 5) & 15, lane = u & 31;
        const uint32_t* src = g_Bfh
            + (((size_t)(bn * 16 + nt) * 16 + ks * 2 + kc) * 32 + lane) * 2;
        CP_ASYNC16(sb + 8192 + c * 16, src);
    }
}

__global__ __launch_bounds__(256, 1)
void k_gemm_mma(float* __restrict__ out) {
    extern __shared__ char sm_[];
    const int t = threadIdx.x, lane = t & 31, wid = t >> 5;
    const int wm = wid >> 2;         // 0..1  (m offset wm*64)
    const int wn = wid & 3;          // 0..3  (n offset wn*32)
    const int g = lane >> 2, tg = lane & 3;
    const int bn = blockIdx.x, bm = blockIdx.y;
    const int n0 = bm * 128, j0 = bn * 128;

    float* sSn = (float*)sm_;
    if (t < 128) sSn[t] = g_Snorm[j0 + t];

    copy_stage(sm_, 0, 0, bm, bn, t);
    CP_COMMIT();

    float acc[4][4][4];
    #pragma unroll
    for (int a = 0; a < 4; a++)
        #pragma unroll
        for (int b = 0; b < 4; b++)
            #pragma unroll
            for (int c = 0; c < 4; c++) acc[a][b][c] = 0.f;

    for (int ks = 0; ks < 8; ks++) {
        CP_WAIT0();
        __syncthreads();
        if (ks + 1 < 8) {
            copy_stage(sm_, (ks + 1) & 1, ks + 1, bm, bn, t);
            CP_COMMIT();
        }
        char* sbase = sm_ + 512 + (ks & 1) * STG;
        #pragma unroll
        for (int kc = 0; kc < 2; kc++) {
            uint32_t ah[4][4], bh[4][2];
            #pragma unroll
            for (int j = 0; j < 4; j++) {
                uint4 x = *(const uint4*)(sbase + ((kc * 8 + wm * 4 + j) * 32 + lane) * 16);
                ah[j][0] = x.x; ah[j][1] = x.y; ah[j][2] = x.z; ah[j][3] = x.w;
                uint2 u = *(const uint2*)(sbase + 8192 + ((kc * 16 + wn * 4 + j) * 32 + lane) * 8);
                bh[j][0] = u.x; bh[j][1] = u.y;
            }
            #pragma unroll
            for (int mt = 0; mt < 4; mt++)
                #pragma unroll
                for (int nt = 0; nt < 4; nt++)
                    mma_f16(acc[mt][nt], ah[mt], bh[nt]);
        }
    }
    __syncthreads();   // stage smem free; reuse for reduction

    float* redD = (float*)(sm_ + 512);

    // d_hh = fl( fl(An+Sj) - 2^-11 * acc ) ; store full tile + per-row min partials
    #pragma unroll
    for (int mt = 0; mt < 4; mt++) {
        int r0 = wm * 64 + mt * 16 + g;
        int r1 = r0 + 8;
        float an0 = g_Anorm[n0 + r0];
        float an1 = g_Anorm[n0 + r1];
        float bd0 = __int_as_float(0x7f800000), bd1 = bd0;
        float2 s0[4], s1[4];
        #pragma unroll
        for (int nt = 0; nt < 4; nt++) {
            #pragma unroll
            for (int e = 0; e < 2; e++) {
                int cl = wn * 32 + nt * 8 + tg * 2 + e;
                float sj = sSn[cl];
                float d0 = __fmaf_rn(-0x1p-11f, acc[mt][nt][e],     __fadd_rn(an0, sj));
                float d1 = __fmaf_rn(-0x1p-11f, acc[mt][nt][2 + e], __fadd_rn(an1, sj));
                if (e) { s0[nt].y = d0; s1[nt].y = d1; }
                else   { s0[nt].x = d0; s1[nt].x = d1; }
                bd0 = fminf(bd0, d0);
                bd1 = fminf(bd1, d1);
            }
        }
        size_t base0 = OFF_OH + (size_t)(n0 + r0) * NCODE + j0 + wn * 32 + tg * 2;
        size_t base1 = OFF_OH + (size_t)(n0 + r1) * NCODE + j0 + wn * 32 + tg * 2;
        #pragma unroll
        for (int nt = 0; nt < 4; nt++) {
            *(float2*)&out[base0 + nt * 8] = s0[nt];
            *(float2*)&out[base1 + nt * 8] = s1[nt];
        }
        #pragma unroll
        for (int off = 1; off <= 2; off <<= 1) {
            bd0 = fminf(bd0, __shfl_xor_sync(0xffffffffu, bd0, off));
            bd1 = fminf(bd1, __shfl_xor_sync(0xffffffffu, bd1, off));
        }
        if (tg == 0) {
            redD[r0 * 4 + wn] = bd0;
            redD[r1 * 4 + wn] = bd1;
        }
    }
    __syncthreads();
    if (t < 128) {
        float bd = redD[t * 4];
        #pragma unroll
        for (int w = 1; w < 4; w++) bd = fminf(bd, redD[t * 4 + w]);
        g_pd[(size_t)(n0 + t) * 32 + bn] = bd;
    }
}

// ---------------------------------------------------------------- refine: screen + exact scalar repair
// one warp per row. Candidates: d_hh < rowmin_hh + MARGIN. Exact d via R3 composition.
__global__ __launch_bounds__(128, 1)
void k_refine(const float* __restrict__ z, const float* __restrict__ E,
              float* __restrict__ out) {
    __shared__ int cand[4][CAP];
    const int lane = threadIdx.x & 31, w = threadIdx.x >> 5;
    const int n = blockIdx.x * 4 + w;

    // rowmin over 32 tile partials
    float pm = g_pd[(size_t)n * 32 + lane];
    #pragma unroll
    for (int off = 16; off > 0; off >>= 1)
        pm = fminf(pm, __shfl_xor_sync(0xffffffffu, pm, off));
    const float thr = pm + MARGIN;

    // stream the row's d_hh, ballot-compact candidates (ascending j)
    const float* Drow = out + OFF_OH + (size_t)n * NCODE;
    int cnt = 0;
    for (int c0 = 0; c0 < NCODE; c0 += 32) {
        float d = Drow[c0 + lane];
        unsigned m = __ballot_sync(0xffffffffu, d < thr);
        if (d < thr) {
            int pos = cnt + __popc(m & ((1u << lane) - 1u));
            if (pos < CAP) cand[w][pos] = c0 + lane;
        }
        cnt += __popc(m);
    }
    __syncwarp();
    int nc = cnt < CAP ? cnt : CAP;

    // exact scalar d (R3 composition: k-sequential fmaf, d = fmaf(-2, acc, an+sj))
    float bd = __int_as_float(0x7f800000);
    int bj = 0x7fffffff;
    const int b = n >> 13, s = n & (SPB - 1);
    const float* zb = z + (size_t)b * (KDIM * SPB) + s;
    if (lane < nc) {
        int j = cand[w][lane];
        const float* e = E + (size_t)j * KDIM;
        float acc = 0.f;
        #pragma unroll 8
        for (int k = 0; k < KDIM; k++)
            acc = __fmaf_rn(zb[(size_t)k * SPB], e[k], acc);
        float an = g_Anorm[n];
        bd = __fmaf_rn(-2.0f, acc, __fadd_rn(an, g_Snorm[j]));
        bj = j;
    }
    #pragma unroll
    for (int off = 16; off > 0; off >>= 1) {
        float d2 = __shfl_xor_sync(0xffffffffu, bd, off);
        int   j2 = __shfl_xor_sync(0xffffffffu, bj, off);
        if (d2 < bd || (d2 == bd && j2 < bj)) { bd = d2; bj = j2; }
    }
    if (lane == 0) {
        g_idx[n] = bj;
        out[OFF_IDX + n] = (float)bj;
        atomicAdd(&g_cnt[bj], 1);
    }
}

// ---------------------------------------------------------------- one-hot rows (overwrites d_hh scratch)
__global__ void k_onehot(float* __restrict__ out) {
    int row = blockIdx.x;
    int t = threadIdx.x;                  // 128 threads, 16 float2 each
    int idx = g_idx[row];
    float2* dst = (float2*)(out + OFF_OH + (size_t)row * NCODE);
    #pragma unroll
    for (int i = 0; i < 16; i++) {
        int p = t * 16 + i;               // float2 slot 0..2047
        float2 v = make_float2(0.f, 0.f);
        if ((idx >> 1) == p) ((idx & 1) ? v.y : v.x) = 1.0f;
        dst[p] = v;
    }
}

// ---------------------------------------------------------------- z_q (straight-through), z_out, loss
__global__ void k_zq_loss(const float* __restrict__ z, const float* __restrict__ E,
                          float* __restrict__ out) {
    size_t i4 = (size_t)blockIdx.x * 256 + threadIdx.x;
    size_t i = i4 * 4;
    int bb = (int)(i >> 21);
    int rem = (int)(i & 2097151u);
    int c = rem >> 13;
    int s = rem & (SPB - 1);
    float4 zp = *(const float4*)(z + i);
    int nbase = bb * SPB + s;
    float zv[4] = {zp.x, zp.y, zp.z, zp.w};
    double ls = 0.0;
    float q[4];
    #pragma unroll
    for (int u = 0; u < 4; u++) {
        int idx = g_idx[nbase + u];
        float e = E[(size_t)idx * KDIM + c];
        float d1 = __fsub_rn(e, zv[u]);
        q[u] = __fadd_rn(zv[u], d1);
        float sq = __fmul_rn(d1, d1);
        ls += (double)sq;
    }
    #pragma unroll
    for (int u = 0; u < 4; u++) {
        out[OFF_ZQ + i + u]   = q[u];
        out[OFF_ZOUT + i + u] = zv[u];
    }
    #pragma unroll
    for (int off = 16; off > 0; off >>= 1)
        ls += __shfl_down_sync(0xffffffffu, ls, off);
    __shared__ double wsum[8];
    int t = threadIdx.x;
    if ((t & 31) == 0) wsum[t >> 5] = ls;
    __syncthreads();
    if (t == 0) {
        double ssum = 0.0;
        #pragma unroll
        for (int w = 0; w < 8; w++) ssum += wsum[w];
        g_losspart[blockIdx.x] = ssum;
    }
}

// ---------------------------------------------------------------- ema update
__global__ void k_ema(const float* __restrict__ E, const float* __restrict__ ema,
                      float* __restrict__ out) {
    int i = blockIdx.x * 256 + threadIdx.x;
    float a = __fmul_rn(0.25f, ema[i]);
    float bq = __fmul_rn(0.75f, E[i]);
    out[OFF_EMA + i] = __fadd_rn(a, bq);
}

// ---------------------------------------------------------------- scalars
__global__ void k_scalars(float* __restrict__ out) {
    __shared__ double sd[256];
    int t = threadIdx.x;
    double a = 0.0;
    for (int i = t; i < 4096; i += 256) a += g_losspart[i];
    sd[t] = a;
    __syncthreads();
    for (int off = 128; off > 0; off >>= 1) {
        if (t < off) sd[t] += sd[t + off];
        __syncthreads();
    }
    if (t == 0) {
        double m = sd[0] / (double)ZTOT;
        float mf = (float)m;
        out[OFF_LOSS] = __fadd_rn(mf, __fmul_rn(0.25f, mf));
    }
    __syncthreads();
    double h = 0.0;
    for (int j = t; j < NCODE; j += 256) {
        double e = (double)g_cnt[j] / (double)NROWS;
        h += e * log(e + 1e-10);
    }
    sd[t] = h;
    __syncthreads();
    for (int off = 128; off > 0; off >>= 1) {
        if (t < off) sd[t] += sd[t + off];
        __syncthreads();
    }
    if (t == 0) out[OFF_PERP] = (float)exp(-sd[0]);
}

// ---------------------------------------------------------------- launch
extern "C" void kernel_launch(void* const* d_in, const int* in_sizes, int n_in,
                              void* d_out, int out_size) {
    const float* z   = (const float*)d_in[0];
    const float* E   = (const float*)d_in[1];
    const float* ema = (const float*)d_in[2];
    float* out = (float*)d_out;

    cudaFuncSetAttribute(k_gemm_mma, cudaFuncAttributeMaxDynamicSharedMemorySize, GSMEM);

    k_init<<<16, 256>>>();
    k_rownorm<<<NROWS / 256, 256>>>(z);
    k_codenorm<<<NCODE / 8, 256>>>(E);
    k_packA<<<2048, 256>>>(z);
    k_packB<<<1024, 256>>>(E);

    k_gemm_mma<<<dim3(NCODE / 128, NROWS / 128), 256, GSMEM>>>(out);

    k_refine<<<NROWS / 4, 128>>>(z, E, out);
    k_onehot<<<NROWS, 128>>>(out);

    k_zq_loss<<<4096, 256>>>(z, E, out);
    k_ema<<<(NCODE * KDIM) / 256, 256>>>(E, ema, out);
    k_scalars<<<1, 256>>>(out);
}